// round 16
// baseline (speedup 1.0000x reference)
#include <cuda_runtime.h>
#include <cuda_fp16.h>
#include <math.h>
#include <stdint.h>

#define D_MODEL 768
#define N_HEADS 12
#define HEAD_DIM 64
#define FFN_DIM 3072
#define T_TOK 2048
#define BATCH 2
#define M_ROWS (BATCH * T_TOK)   // 4096
#define QKV_N 2304               // 3 * D_MODEL

// -------------------- scratch ---------------------------------------------
__device__ __half g_ni[M_ROWS * D_MODEL];
__device__ __half g_qkv[M_ROWS * QKV_N];
__device__ __half g_wqkvT[QKV_N * D_MODEL];
__device__ float  g_bqkv[QKV_N];
__device__ __half g_woT[D_MODEL * D_MODEL];
__device__ __half g_w1T[FFN_DIM * D_MODEL];
__device__ __half g_w2T[D_MODEL * FFN_DIM];
__device__ __half g_attn[M_ROWS * D_MODEL];
__device__ float  g_res1[M_ROWS * D_MODEL];
__device__ __half g_ffin[M_ROWS * D_MODEL];
__device__ __half g_h[M_ROWS * FFN_DIM];
__device__ float  g_trig[T_TOK * 16 * 2];

// -------------------- helpers ---------------------------------------------
__device__ __forceinline__ unsigned su32(const void* p) {
    return (unsigned)__cvta_generic_to_shared(p);
}
__device__ __forceinline__ void cp16(void* smem_dst, const void* gptr) {
    asm volatile("cp.async.cg.shared.global [%0], [%1], 16;" :: "r"(su32(smem_dst)), "l"(gptr));
}
__device__ __forceinline__ void cp_commit() { asm volatile("cp.async.commit_group;"); }
template <int NN>
__device__ __forceinline__ void cp_wait() { asm volatile("cp.async.wait_group %0;" :: "n"(NN)); }

__device__ __forceinline__ void mma_f16(float* c, const unsigned* a, unsigned b0, unsigned b1) {
    asm volatile(
        "mma.sync.aligned.m16n8k16.row.col.f32.f16.f16.f32 "
        "{%0,%1,%2,%3}, {%4,%5,%6,%7}, {%8,%9}, {%0,%1,%2,%3};"
        : "+f"(c[0]), "+f"(c[1]), "+f"(c[2]), "+f"(c[3])
        : "r"(a[0]), "r"(a[1]), "r"(a[2]), "r"(a[3]), "r"(b0), "r"(b1));
}
__device__ __forceinline__ void ldsm4(unsigned* r, unsigned addr) {
    asm volatile("ldmatrix.sync.aligned.m8n8.x4.shared.b16 {%0,%1,%2,%3}, [%4];"
                 : "=r"(r[0]), "=r"(r[1]), "=r"(r[2]), "=r"(r[3]) : "r"(addr));
}
__device__ __forceinline__ void ldsm4t(unsigned* r, unsigned addr) {
    asm volatile("ldmatrix.sync.aligned.m8n8.x4.trans.shared.b16 {%0,%1,%2,%3}, [%4];"
                 : "=r"(r[0]), "=r"(r[1]), "=r"(r[2]), "=r"(r[3]) : "r"(addr));
}
// two exponentials in one MUFU op, result already packed as half2 fragment
__device__ __forceinline__ unsigned ex2_h2(float a, float b) {
    __half2 t = __floats2half2_rn(a, b);
    unsigned u = *(unsigned*)&t, r;
    asm("ex2.approx.f16x2 %0, %1;" : "=r"(r) : "r"(u));
    return r;
}

// -------------------- warp-per-row LayerNorm ------------------------------
__global__ void ln_warp(const float* __restrict__ x, const float* __restrict__ g,
                        const float* __restrict__ bta, __half* __restrict__ y) {
    int w = (blockIdx.x * blockDim.x + threadIdx.x) >> 5;
    int lane = threadIdx.x & 31;
    if (w >= M_ROWS) return;
    const float* xr = x + (size_t)w * D_MODEL;
    float4 v[6];
    float sum = 0.f;
#pragma unroll
    for (int i = 0; i < 6; i++) {
        v[i] = *(const float4*)(xr + i * 128 + lane * 4);
        sum += v[i].x + v[i].y + v[i].z + v[i].w;
    }
#pragma unroll
    for (int o = 16; o; o >>= 1) sum += __shfl_xor_sync(0xffffffffu, sum, o);
    float mu = sum * (1.f / 768.f);
    float var = 0.f;
#pragma unroll
    for (int i = 0; i < 6; i++) {
        v[i].x -= mu; v[i].y -= mu; v[i].z -= mu; v[i].w -= mu;
        var += v[i].x * v[i].x + v[i].y * v[i].y + v[i].z * v[i].z + v[i].w * v[i].w;
    }
#pragma unroll
    for (int o = 16; o; o >>= 1) var += __shfl_xor_sync(0xffffffffu, var, o);
    float rs = rsqrtf(var * (1.f / 768.f) + 1e-5f);
    __half* yr = y + (size_t)w * D_MODEL;
#pragma unroll
    for (int i = 0; i < 6; i++) {
        int col = i * 128 + lane * 4;
        float4 gv = *(const float4*)(g + col);
        float4 bv = *(const float4*)(bta + col);
        __half2 h0 = __floats2half2_rn(v[i].x * rs * gv.x + bv.x, v[i].y * rs * gv.y + bv.y);
        __half2 h1 = __floats2half2_rn(v[i].z * rs * gv.z + bv.z, v[i].w * rs * gv.w + bv.w);
        *(__half2*)(yr + col) = h0;
        *(__half2*)(yr + col + 2) = h1;
    }
}

// -------------------- merged prep: transposes + trig + bias ----------------
// blocks [0,6912): weight transposes | [6912,7040): trig | [7040,7049): bias
__global__ void prep_all(const float* __restrict__ wq, const float* __restrict__ wk,
                         const float* __restrict__ wv, const float* __restrict__ wo,
                         const float* __restrict__ w1, const float* __restrict__ w2,
                         const float* __restrict__ bq, const float* __restrict__ bk,
                         const float* __restrict__ bv,
                         __half* __restrict__ wqkvT, __half* __restrict__ woT,
                         __half* __restrict__ w1T, __half* __restrict__ w2T,
                         float* __restrict__ trig, float* __restrict__ bqkv) {
    __shared__ float t[32][33];
    int bid = blockIdx.x;
    int x = threadIdx.x, y = threadIdx.y;
    int tid = y * 32 + x;
    if (bid >= 6912) {
        if (bid < 7040) {
            int idx = (bid - 6912) * 256 + tid;
            int tt = idx >> 4, i = idx & 15;
            double ts = pow(10000.0, (double)i / 32.0);
            double ang = (double)tt / ts;
            double sd, cd;
            sincos(ang, &sd, &cd);
            trig[idx * 2]     = (float)cd;
            trig[idx * 2 + 1] = (float)sd;
        } else {
            int j = (bid - 7040) * 256 + tid;
            if (j < 768) bqkv[j] = bq[j] * 0.125f;
            else if (j < 1536) bqkv[j] = bk[j - 768];
            else if (j < 2304) bqkv[j] = bv[j - 1536];
        }
        return;
    }
    const float* src;
    __half* dst;
    int R, C, bx, by;
    float scale = 1.f;
    if (bid < 2304) {
        int seg = bid / 576, r = bid % 576;
        bx = r % 24; by = r / 24; R = 768; C = 768;
        if (seg == 0)      { src = wq; dst = wqkvT; scale = 0.125f; }
        else if (seg == 1) { src = wk; dst = wqkvT + 768 * 768; }
        else if (seg == 2) { src = wv; dst = wqkvT + 1536 * 768; }
        else               { src = wo; dst = woT; }
    } else if (bid < 4608) {
        int r = bid - 2304;
        bx = r % 96; by = r / 96; R = 768; C = 3072;
        src = w1; dst = w1T;
    } else {
        int r = bid - 4608;
        bx = r % 24; by = r / 24; R = 3072; C = 768;
        src = w2; dst = w2T;
    }
    int X = bx * 32, Y = by * 32;
#pragma unroll
    for (int i = 0; i < 32; i += 8)
        t[y + i][x] = src[(size_t)(Y + y + i) * C + X + x] * scale;
    __syncthreads();
#pragma unroll
    for (int i = 0; i < 32; i += 8)
        dst[(size_t)(X + y + i) * R + Y + x] = __float2half(t[x][y + i]);
}

// ==================== fp16 GEMM 128x128, BK=64, 3-stage ====================
#define HSTB 72
#define AHB_SZ (128 * HSTB)
#define G128_SMEM_BYTES (3 * 2 * AHB_SZ * 2)
#define AH64B_SZ (64 * HSTB)
#define G64_SMEM_BYTES (2 * (AH64B_SZ + AHB_SZ) * 2)

template <bool GELU, bool OUTH, bool ROPE>
__global__ __launch_bounds__(256, 2)
void gemm_f16(const __half* __restrict__ A, const __half* __restrict__ BmT,
              const float* __restrict__ bias, const float* __restrict__ res,
              void* __restrict__ Cv, const float* __restrict__ trig,
              int M, int N, int K) {
    extern __shared__ __half hsm[];
    __half* AsB = hsm;
    __half* BsB = hsm + 3 * AHB_SZ;
    int tid = threadIdx.x;
    int wid = tid >> 5, lane = tid & 31;
    int g = lane >> 2, tig = lane & 3;
    int wm = wid & 3, wn = wid >> 2;
    int brow = blockIdx.y * 128, bcol = blockIdx.x * 128;

    const __half* apre[4];
    const __half* bpre[4];
    int aso[4];
#pragma unroll
    for (int i = 0; i < 4; i++) {
        int idx = tid + i * 256;
        int row = idx >> 3, ch = (idx & 7) * 8;
        aso[i] = row * HSTB + ch;
        apre[i] = A + (size_t)(brow + row) * K + ch;
        bpre[i] = BmT + (size_t)(bcol + row) * K + ch;
    }

    int nIter = K >> 6;

#define GF_ISSUE(KT, STG) do {                                                \
        __half* asd_ = AsB + (STG) * AHB_SZ;                                  \
        __half* bsd_ = BsB + (STG) * AHB_SZ;                                  \
        _Pragma("unroll")                                                     \
        for (int i = 0; i < 4; i++) {                                         \
            cp16(&asd_[aso[i]], apre[i] + (KT) * 64);                         \
            cp16(&bsd_[aso[i]], bpre[i] + (KT) * 64);                         \
        }                                                                     \
        cp_commit();                                                           \
    } while (0)

    GF_ISSUE(0, 0);
    GF_ISSUE(1, 1);

    float acc[2][8][4];
#pragma unroll
    for (int i = 0; i < 2; i++)
#pragma unroll
        for (int j = 0; j < 8; j++)
#pragma unroll
            for (int r = 0; r < 4; r++) acc[i][j][r] = 0.f;

    int l15 = lane & 15, lkh8 = (lane >> 4) << 3;

    int cur = 0, nxt = 2;
    for (int kt = 0; kt < nIter; ++kt) {
        if (kt + 1 < nIter) cp_wait<1>(); else cp_wait<0>();
        __syncthreads();
        if (kt + 2 < nIter) GF_ISSUE(kt + 2, nxt);
        const __half* As = AsB + cur * AHB_SZ;
        const __half* Bs = BsB + cur * AHB_SZ;
#pragma unroll
        for (int ks = 0; ks < 64; ks += 16) {
            unsigned af[2][4];
#pragma unroll
            for (int mt = 0; mt < 2; mt++) {
                int R = wm * 32 + mt * 16;
                ldsm4(af[mt], su32(&As[(R + l15) * HSTB + ks + lkh8]));
            }
#pragma unroll
            for (int p = 0; p < 4; p++) {
                unsigned bf[4];
                int nr = wn * 64 + p * 16;
                ldsm4(bf, su32(&Bs[(nr + l15) * HSTB + ks + lkh8]));
                mma_f16(acc[0][2 * p],     af[0], bf[0], bf[2]);
                mma_f16(acc[1][2 * p],     af[1], bf[0], bf[2]);
                mma_f16(acc[0][2 * p + 1], af[0], bf[1], bf[3]);
                mma_f16(acc[1][2 * p + 1], af[1], bf[1], bf[3]);
            }
        }
        cur = cur + 1; if (cur == 3) cur = 0;
        nxt = nxt + 1; if (nxt == 3) nxt = 0;
    }
#undef GF_ISSUE

#pragma unroll
    for (int mt = 0; mt < 2; mt++) {
        int row0 = brow + wm * 32 + mt * 16 + g;
        int t0 = row0 & (T_TOK - 1);
        int t1 = (row0 + 8) & (T_TOK - 1);
        bool doRope = ROPE && (bcol + wn * 64) < 1536;
#pragma unroll
        for (int nt2 = 0; nt2 < 4; nt2++) {
            int ntA = nt2, ntB = nt2 + 4;
            int colA = bcol + wn * 64 + ntA * 8 + tig * 2;
            int colB = colA + 32;
            float bA0 = bias[colA], bA1 = bias[colA + 1];
            float bB0 = bias[colB], bB1 = bias[colB + 1];
            float vA00 = acc[mt][ntA][0] + bA0, vA01 = acc[mt][ntA][1] + bA1;
            float vA10 = acc[mt][ntA][2] + bA0, vA11 = acc[mt][ntA][3] + bA1;
            float vB00 = acc[mt][ntB][0] + bB0, vB01 = acc[mt][ntB][1] + bB1;
            float vB10 = acc[mt][ntB][2] + bB0, vB11 = acc[mt][ntB][3] + bB1;
            if (doRope && nt2 < 2) {
                int i0 = ntA * 8 + tig * 2;
                float c00 = trig[(t0 * 16 + i0) * 2],     s00 = trig[(t0 * 16 + i0) * 2 + 1];
                float c01 = trig[(t0 * 16 + i0 + 1) * 2], s01 = trig[(t0 * 16 + i0 + 1) * 2 + 1];
                float c10 = trig[(t1 * 16 + i0) * 2],     s10 = trig[(t1 * 16 + i0) * 2 + 1];
                float c11 = trig[(t1 * 16 + i0 + 1) * 2], s11 = trig[(t1 * 16 + i0 + 1) * 2 + 1];
                float x1, x2;
                x1 = vA00; x2 = vB00; vA00 = x1 * c00 - x2 * s00; vB00 = x2 * c00 + x1 * s00;
                x1 = vA01; x2 = vB01; vA01 = x1 * c01 - x2 * s01; vB01 = x2 * c01 + x1 * s01;
                x1 = vA10; x2 = vB10; vA10 = x1 * c10 - x2 * s10; vB10 = x2 * c10 + x1 * s10;
                x1 = vA11; x2 = vB11; vA11 = x1 * c11 - x2 * s11; vB11 = x2 * c11 + x1 * s11;
            }
            if (GELU) {
                vA00 *= normcdff(vA00); vA01 *= normcdff(vA01);
                vA10 *= normcdff(vA10); vA11 *= normcdff(vA11);
                vB00 *= normcdff(vB00); vB01 *= normcdff(vB01);
                vB10 *= normcdff(vB10); vB11 *= normcdff(vB11);
            }
            if (res) {
                const float* r0A = res + (size_t)row0 * N + colA;
                const float* r1A = res + (size_t)(row0 + 8) * N + colA;
                vA00 += r0A[0]; vA01 += r0A[1]; vA10 += r1A[0]; vA11 += r1A[1];
                const float* r0B = res + (size_t)row0 * N + colB;
                const float* r1B = res + (size_t)(row0 + 8) * N + colB;
                vB00 += r0B[0]; vB01 += r0B[1]; vB10 += r1B[0]; vB11 += r1B[1];
            }
            if (OUTH) {
                __half* Ch = (__half*)Cv;
                *(__half2*)(Ch + (size_t)row0 * N + colA) = __floats2half2_rn(vA00, vA01);
                *(__half2*)(Ch + (size_t)(row0 + 8) * N + colA) = __floats2half2_rn(vA10, vA11);
                *(__half2*)(Ch + (size_t)row0 * N + colB) = __floats2half2_rn(vB00, vB01);
                *(__half2*)(Ch + (size_t)(row0 + 8) * N + colB) = __floats2half2_rn(vB10, vB11);
            } else {
                float* Cf = (float*)Cv;
                *(float2*)(Cf + (size_t)row0 * N + colA) = make_float2(vA00, vA01);
                *(float2*)(Cf + (size_t)(row0 + 8) * N + colA) = make_float2(vA10, vA11);
                *(float2*)(Cf + (size_t)row0 * N + colB) = make_float2(vB00, vB01);
                *(float2*)(Cf + (size_t)(row0 + 8) * N + colB) = make_float2(vB10, vB11);
            }
        }
    }
}

// ==================== fp16 GEMM 64x128, BK=64, 2-stage =====================
template <bool GELU, bool OUTH>
__global__ __launch_bounds__(256, 3)
void gemm_f16_m64(const __half* __restrict__ A, const __half* __restrict__ BmT,
                  const float* __restrict__ bias, const float* __restrict__ res,
                  void* __restrict__ Cv, int M, int N, int K) {
    extern __shared__ __half hsm[];
    __half* AsB = hsm;
    __half* BsB = hsm + 2 * AH64B_SZ;
    int tid = threadIdx.x;
    int wid = tid >> 5, lane = tid & 31;
    int g = lane >> 2, tig = lane & 3;
    int wm = wid & 1, wn = wid >> 1;
    int brow = blockIdx.y * 64, bcol = blockIdx.x * 128;

    const __half* apre[2];
    int aso[2];
#pragma unroll
    for (int i = 0; i < 2; i++) {
        int idx = tid + i * 256;
        int row = idx >> 3, ch = (idx & 7) * 8;
        aso[i] = row * HSTB + ch;
        apre[i] = A + (size_t)(brow + row) * K + ch;
    }
    const __half* bpre[4];
    int bso[4];
#pragma unroll
    for (int i = 0; i < 4; i++) {
        int idx = tid + i * 256;
        int row = idx >> 3, ch = (idx & 7) * 8;
        bso[i] = row * HSTB + ch;
        bpre[i] = BmT + (size_t)(bcol + row) * K + ch;
    }

    int nIter = K >> 6;

#define GF_ISSUE64(KT, STG) do {                                              \
        __half* asd_ = AsB + (STG) * AH64B_SZ;                                \
        __half* bsd_ = BsB + (STG) * AHB_SZ;                                  \
        _Pragma("unroll")                                                     \
        for (int i = 0; i < 2; i++)                                           \
            cp16(&asd_[aso[i]], apre[i] + (KT) * 64);                         \
        _Pragma("unroll")                                                     \
        for (int i = 0; i < 4; i++)                                           \
            cp16(&bsd_[bso[i]], bpre[i] + (KT) * 64);                         \
        cp_commit();                                                           \
    } while (0)

    GF_ISSUE64(0, 0);

    float acc[2][4][4];
#pragma unroll
    for (int i = 0; i < 2; i++)
#pragma unroll
        for (int j = 0; j < 4; j++)
#pragma unroll
            for (int r = 0; r < 4; r++) acc[i][j][r] = 0.f;

    int l15 = lane & 15, lkh8 = (lane >> 4) << 3;

    for (int kt = 0; kt < nIter; ++kt) {
        int cur = kt & 1;
        cp_wait<0>();
        __syncthreads();
        if (kt + 1 < nIter) GF_ISSUE64(kt + 1, cur ^ 1);
        const __half* As = AsB + cur * AH64B_SZ;
        const __half* Bs = BsB + cur * AHB_SZ;
#pragma unroll
        for (int ks = 0; ks < 64; ks += 16) {
            unsigned af[2][4];
#pragma unroll
            for (int mt = 0; mt < 2; mt++) {
                int R = wm * 32 + mt * 16;
                ldsm4(af[mt], su32(&As[(R + l15) * HSTB + ks + lkh8]));
            }
#pragma unroll
            for (int p = 0; p < 2; p++) {
                unsigned bf[4];
                int nr = wn * 32 + p * 16;
                ldsm4(bf, su32(&Bs[(nr + l15) * HSTB + ks + lkh8]));
                mma_f16(acc[0][2 * p],     af[0], bf[0], bf[2]);
                mma_f16(acc[1][2 * p],     af[1], bf[0], bf[2]);
                mma_f16(acc[0][2 * p + 1], af[0], bf[1], bf[3]);
                mma_f16(acc[1][2 * p + 1], af[1], bf[1], bf[3]);
            }
        }
    }
#undef GF_ISSUE64

#pragma unroll
    for (int mt = 0; mt < 2; mt++) {
        int row0 = brow + wm * 32 + mt * 16 + g;
#pragma unroll
        for (int nt = 0; nt < 4; nt++) {
            int col = bcol + wn * 32 + nt * 8 + tig * 2;
            float b0 = bias[col], b1 = bias[col + 1];
            float v00 = acc[mt][nt][0] + b0;
            float v01 = acc[mt][nt][1] + b1;
            float v10 = acc[mt][nt][2] + b0;
            float v11 = acc[mt][nt][3] + b1;
            if (GELU) {
                v00 *= normcdff(v00); v01 *= normcdff(v01);
                v10 *= normcdff(v10); v11 *= normcdff(v11);
            }
            if (res) {
                const float* r0p = res + (size_t)row0 * N + col;
                const float* r1p = res + (size_t)(row0 + 8) * N + col;
                v00 += r0p[0]; v01 += r0p[1];
                v10 += r1p[0]; v11 += r1p[1];
            }
            if (OUTH) {
                __half* Ch = (__half*)Cv;
                *(__half2*)(Ch + (size_t)row0 * N + col) = __floats2half2_rn(v00, v01);
                *(__half2*)(Ch + (size_t)(row0 + 8) * N + col) = __floats2half2_rn(v10, v11);
            } else {
                float* Cf = (float*)Cv;
                *(float2*)(Cf + (size_t)row0 * N + col) = make_float2(v00, v01);
                *(float2*)(Cf + (size_t)(row0 + 8) * N + col) = make_float2(v10, v11);
            }
        }
    }
}

// ==================== fp16 flash attention: ex2.f16x2 softmax ==============
#define QHS 72
#define KV_SZ (128 * QHS)
#define AT_SMEM_BYTES ((128 * QHS + 4 * KV_SZ) * 2)
#define L2E 1.4426950408889634f

__global__ __launch_bounds__(256, 2)
void attn_f16(const __half* __restrict__ QKV, const float* __restrict__ ab,
              __half* __restrict__ O) {
    extern __shared__ __half hsm[];
    __half* Qh = hsm;
    __half* KhB = Qh + 128 * QHS;
    __half* VhB = KhB + 2 * KV_SZ;

    int tid = threadIdx.x;
    int wid = tid >> 5, lane = tid & 31;
    int g = lane >> 2, tig = lane & 3;
    int m0 = wid * 16;
    int l15 = lane & 15, lkh8 = (lane >> 4) << 3;

    int qb = blockIdx.x * 128;
    int h = blockIdx.y, b = blockIdx.z;
    size_t bh = (size_t)b * T_TOK * QKV_N + h * HEAD_DIM;
    const __half* qp = QKV + bh;
    const __half* kp = QKV + bh + 768;
    const __half* vp = QKV + bh + 1536;

#define G_ISSUE(KT, BUF) do {                                                 \
        int kb_ = (KT) * 128;                                                 \
        __half* kd_ = KhB + (BUF) * KV_SZ;                                    \
        __half* vd_ = VhB + (BUF) * KV_SZ;                                    \
        _Pragma("unroll")                                                     \
        for (int it = 0; it < 4; it++) {                                      \
            int idx_ = tid + it * 256;                                        \
            int r_ = idx_ >> 3, c_ = (idx_ & 7) * 8;                          \
            cp16(&kd_[r_ * QHS + c_], kp + (size_t)(kb_ + r_) * QKV_N + c_);  \
            cp16(&vd_[r_ * QHS + c_], vp + (size_t)(kb_ + r_) * QKV_N + c_);  \
        }                                                                     \
        cp_commit();                                                          \
    } while (0)

#pragma unroll
    for (int it = 0; it < 4; it++) {
        int idx = tid + it * 256;
        int r = idx >> 3, c = (idx & 7) * 8;
        cp16(&Qh[r * QHS + c], qp + (size_t)(qb + r) * QKV_N + c);
    }
    cp_commit();
    G_ISSUE(0, 0);

    cp_wait<1>();
    __syncthreads();
    unsigned qf[4][4];
#pragma unroll
    for (int ks4 = 0; ks4 < 4; ks4++)
        ldsm4(qf[ks4], su32(&Qh[(m0 + l15) * QHS + ks4 * 16 + lkh8]));

    float mo0 = -1e30f, mo1 = -1e30f, l0 = 0.f, l1 = 0.f;
    float o[8][4];
#pragma unroll
    for (int nt = 0; nt < 8; nt++)
#pragma unroll
        for (int r = 0; r < 4; r++) o[nt][r] = 0.f;

    float bias0 = ab[h * 2 + 0], bias1 = ab[h * 2 + 1];
    int qvar = qb >> 7;

    for (int kt = 0; kt < 16; kt++) {
        cp_wait<0>();
        __syncthreads();
        int cur = kt & 1;
        if (kt + 1 < 16) G_ISSUE(kt + 1, cur ^ 1);
        float bias = (kt == qvar) ? bias0 : bias1;

#pragma unroll
        for (int hh = 0; hh < 2; hh++) {
            const __half* Kh = KhB + cur * KV_SZ + hh * 64 * QHS;
            const __half* Vh = VhB + cur * KV_SZ + hh * 64 * QHS;

            float s[8][4];
#pragma unroll
            for (int nt = 0; nt < 8; nt++)
#pragma unroll
                for (int r = 0; r < 4; r++) s[nt][r] = 0.f;
#pragma unroll
            for (int ks4 = 0; ks4 < 4; ks4++) {
#pragma unroll
                for (int p = 0; p < 4; p++) {
                    unsigned bf[4];
                    ldsm4(bf, su32(&Kh[(p * 16 + l15) * QHS + ks4 * 16 + lkh8]));
                    mma_f16(s[2 * p],     qf[ks4], bf[0], bf[2]);
                    mma_f16(s[2 * p + 1], qf[ks4], bf[1], bf[3]);
                }
            }

            float mx0 = mo0, mx1 = mo1;
#pragma unroll
            for (int nt = 0; nt < 8; nt++) {
                s[nt][0] += bias; s[nt][1] += bias; s[nt][2] += bias; s[nt][3] += bias;
                mx0 = fmaxf(mx0, fmaxf(s[nt][0], s[nt][1]));
                mx1 = fmaxf(mx1, fmaxf(s[nt][2], s[nt][3]));
            }
            mx0 = fmaxf(mx0, __shfl_xor_sync(0xffffffffu, mx0, 1));
            mx0 = fmaxf(mx0, __shfl_xor_sync(0xffffffffu, mx0, 2));
            mx1 = fmaxf(mx1, __shfl_xor_sync(0xffffffffu, mx1, 1));
            mx1 = fmaxf(mx1, __shfl_xor_sync(0xffffffffu, mx1, 2));
            float scl0 = __expf(mo0 - mx0), scl1 = __expf(mo1 - mx1);
            // exp in log2 domain, 2 values per MUFU, result = packed half2 P frag
            float c0 = -mx0 * L2E, c1 = -mx1 * L2E;
            unsigned p01[8], p23[8];
            float sum0 = 0.f, sum1 = 0.f;
#pragma unroll
            for (int nt = 0; nt < 8; nt++) {
                p01[nt] = ex2_h2(fmaf(s[nt][0], L2E, c0), fmaf(s[nt][1], L2E, c0));
                p23[nt] = ex2_h2(fmaf(s[nt][2], L2E, c1), fmaf(s[nt][3], L2E, c1));
                float2 f01 = __half22float2(*(__half2*)&p01[nt]);
                float2 f23 = __half22float2(*(__half2*)&p23[nt]);
                sum0 += f01.x + f01.y;
                sum1 += f23.x + f23.y;
            }
            sum0 += __shfl_xor_sync(0xffffffffu, sum0, 1);
            sum0 += __shfl_xor_sync(0xffffffffu, sum0, 2);
            sum1 += __shfl_xor_sync(0xffffffffu, sum1, 1);
            sum1 += __shfl_xor_sync(0xffffffffu, sum1, 2);
            l0 = l0 * scl0 + sum0; mo0 = mx0;
            l1 = l1 * scl1 + sum1; mo1 = mx1;
#pragma unroll
            for (int nt = 0; nt < 8; nt++) {
                o[nt][0] *= scl0; o[nt][1] *= scl0;
                o[nt][2] *= scl1; o[nt][3] *= scl1;
            }

#pragma unroll
            for (int p = 0; p < 4; p++) {
                unsigned af2[4];
                af2[0] = p01[2 * p];
                af2[1] = p23[2 * p];
                af2[2] = p01[2 * p + 1];
                af2[3] = p23[2 * p + 1];
#pragma unroll
                for (int cbt = 0; cbt < 4; cbt++) {
                    unsigned bf[4];
                    ldsm4t(bf, su32(&Vh[(p * 16 + l15) * QHS + cbt * 16 + lkh8]));
                    mma_f16(o[2 * cbt],     af2, bf[0], bf[1]);
                    mma_f16(o[2 * cbt + 1], af2, bf[2], bf[3]);
                }
            }
        }
    }
#undef G_ISSUE

    float inv0 = 1.f / l0, inv1 = 1.f / l1;
    int row0 = qb + m0 + g;
#pragma unroll
    for (int nt = 0; nt < 8; nt++) {
        int col = nt * 8 + tig * 2;
        __half* o0 = O + (size_t)(b * T_TOK + row0) * D_MODEL + h * HEAD_DIM + col;
        __half* o1 = O + (size_t)(b * T_TOK + row0 + 8) * D_MODEL + h * HEAD_DIM + col;
        *(__half2*)o0 = __floats2half2_rn(o[nt][0] * inv0, o[nt][1] * inv0);
        *(__half2*)o1 = __floats2half2_rn(o[nt][2] * inv1, o[nt][3] * inv1);
    }
}

// -------------------- launch ----------------------------------------------
extern "C" void kernel_launch(void* const* d_in, const int* in_sizes, int n_in,
                              void* d_out, int out_size) {
    const float* hs  = (const float*)d_in[0];
    const float* wq  = (const float*)d_in[1];
    const float* bq  = (const float*)d_in[2];
    const float* wk  = (const float*)d_in[3];
    const float* bk  = (const float*)d_in[4];
    const float* wv  = (const float*)d_in[5];
    const float* bv  = (const float*)d_in[6];
    const float* wo  = (const float*)d_in[7];
    const float* bo  = (const float*)d_in[8];
    const float* ab  = (const float*)d_in[9];
    const float* g1  = (const float*)d_in[10];
    const float* be1 = (const float*)d_in[11];
    const float* g3  = (const float*)d_in[12];
    const float* be3 = (const float*)d_in[13];
    const float* w1  = (const float*)d_in[14];
    const float* b1  = (const float*)d_in[15];
    const float* w2  = (const float*)d_in[16];
    const float* b2  = (const float*)d_in[17];
    float* out = (float*)d_out;

    __half *ni, *qkv, *wqkvT, *woT, *w1T, *w2T, *attn, *ffin, *hbuf;
    float *bqkv, *res1, *trig;
    cudaGetSymbolAddress((void**)&ni,    g_ni);
    cudaGetSymbolAddress((void**)&qkv,   g_qkv);
    cudaGetSymbolAddress((void**)&wqkvT, g_wqkvT);
    cudaGetSymbolAddress((void**)&bqkv,  g_bqkv);
    cudaGetSymbolAddress((void**)&woT,   g_woT);
    cudaGetSymbolAddress((void**)&w1T,   g_w1T);
    cudaGetSymbolAddress((void**)&w2T,   g_w2T);
    cudaGetSymbolAddress((void**)&attn,  g_attn);
    cudaGetSymbolAddress((void**)&res1,  g_res1);
    cudaGetSymbolAddress((void**)&ffin,  g_ffin);
    cudaGetSymbolAddress((void**)&hbuf,  g_h);
    cudaGetSymbolAddress((void**)&trig,  g_trig);

    static bool attr_set = false;
    if (!attr_set) {
        cudaFuncSetAttribute(attn_f16, cudaFuncAttributeMaxDynamicSharedMemorySize,
                             AT_SMEM_BYTES);
        cudaFuncSetAttribute((gemm_f16<false, true, true>), cudaFuncAttributeMaxDynamicSharedMemorySize,
                             G128_SMEM_BYTES);
        cudaFuncSetAttribute((gemm_f16<true, true, false>), cudaFuncAttributeMaxDynamicSharedMemorySize,
                             G128_SMEM_BYTES);
        cudaFuncSetAttribute((gemm_f16_m64<false, false>), cudaFuncAttributeMaxDynamicSharedMemorySize,
                             G64_SMEM_BYTES);
        attr_set = true;
    }

    // 0. prep: transposes + trig + bias in ONE launch
    prep_all<<<7049, dim3(32, 8)>>>(wq, wk, wv, wo, w1, w2, bq, bk, bv,
                                    wqkvT, woT, w1T, w2T, trig, bqkv);

    // 1. LN1 -> fp16
    ln_warp<<<M_ROWS / 8, 256>>>(hs, g1, be1, ni);

    // 2. fused QKV projection + RoPE
    gemm_f16<false, true, true><<<dim3(QKV_N / 128, M_ROWS / 128), 256, G128_SMEM_BYTES>>>(
        ni, wqkvT, bqkv, nullptr, qkv, trig, M_ROWS, QKV_N, D_MODEL);

    // 3. attention
    {
        dim3 ga(T_TOK / 128, N_HEADS, BATCH);
        attn_f16<<<ga, 256, AT_SMEM_BYTES>>>(qkv, ab, attn);
    }

    // 4. out-proj + residual(hs)
    gemm_f16_m64<false, false><<<dim3(D_MODEL / 128, M_ROWS / 64), 256, G64_SMEM_BYTES>>>(
        attn, woT, bo, hs, res1, M_ROWS, D_MODEL, D_MODEL);

    // 5. LN3 -> fp16
    ln_warp<<<M_ROWS / 8, 256>>>(res1, g3, be3, ffin);

    // 6. FFN1 + GELU
    gemm_f16<true, true, false><<<dim3(FFN_DIM / 128, M_ROWS / 128), 256, G128_SMEM_BYTES>>>(
        ffin, w1T, b1, nullptr, hbuf, nullptr, M_ROWS, FFN_DIM, D_MODEL);

    // 7. FFN2 + residual(res1)
    gemm_f16_m64<false, false><<<dim3(D_MODEL / 128, M_ROWS / 64), 256, G64_SMEM_BYTES>>>(
        hbuf, w2T, b2, res1, out, M_ROWS, D_MODEL, FFN_DIM);
}